// round 12
// baseline (speedup 1.0000x reference)
#include <cuda_runtime.h>
#include <cuda_fp16.h>
#include <math.h>
#include <stdint.h>

#define N_TOK 4096
#define DIMD  1024
#define HID   4096
#define OUTD  1024
#define NE    8
#define RMAX  (2*N_TOK)

// ---------------- scratch (static device globals) ----------------
__device__ __half g_xh[(size_t)N_TOK * DIMD];      //  8 MB x fp16 (token order)
__device__ __half g_hh[(size_t)RMAX * HID];        // 64 MB GEMM1 out (fp16, expert-sorted)
__device__ __half g_yh[(size_t)RMAX * OUTD];       // 16 MB GEMM2 out (fp16)
__device__ __half g_w1h[(size_t)NE * DIMD * HID];  // 64 MB
__device__ __half g_w2h[(size_t)NE * HID * OUTD];  // 64 MB
__device__ int   g_perm[RMAX];
__device__ float g_wgt[RMAX];
__device__ int   g_rowpos[N_TOK * 2];
__device__ int   g_sel[N_TOK * 2];
__device__ float g_w[N_TOK * 2];
__device__ int   g_cnt[NE];
__device__ int   g_off[NE];

// ---------------- helpers ----------------
__device__ __forceinline__ void cp16(void* dst, const void* src) {
    unsigned sd = (unsigned)__cvta_generic_to_shared(dst);
    asm volatile("cp.async.cg.shared.global [%0], [%1], 16;" :: "r"(sd), "l"(src));
}
__device__ __forceinline__ uint32_t smem_u32(const void* p) {
    uint32_t a;
    asm("{ .reg .u64 t; cvta.to.shared.u64 t, %1; cvt.u32.u64 %0, t; }" : "=r"(a) : "l"(p));
    return a;
}
__device__ __forceinline__ void ldm4(uint32_t r[4], uint32_t addr) {
    asm volatile("ldmatrix.sync.aligned.m8n8.x4.shared.b16 {%0,%1,%2,%3}, [%4];"
        : "=r"(r[0]), "=r"(r[1]), "=r"(r[2]), "=r"(r[3]) : "r"(addr));
}
__device__ __forceinline__ void ldm4t(uint32_t r[4], uint32_t addr) {
    asm volatile("ldmatrix.sync.aligned.m8n8.x4.trans.shared.b16 {%0,%1,%2,%3}, [%4];"
        : "=r"(r[0]), "=r"(r[1]), "=r"(r[2]), "=r"(r[3]) : "r"(addr));
}
__device__ __forceinline__ void mma16816(float c[4], const uint32_t a[4], const uint32_t* b) {
    asm volatile("mma.sync.aligned.m16n8k16.row.col.f32.f16.f16.f32 "
        "{%0,%1,%2,%3}, {%4,%5,%6,%7}, {%8,%9}, {%0,%1,%2,%3};"
        : "+f"(c[0]), "+f"(c[1]), "+f"(c[2]), "+f"(c[3])
        : "r"(a[0]), "r"(a[1]), "r"(a[2]), "r"(a[3]), "r"(b[0]), "r"(b[1]));
}

#define SW128(x) ((x) ^ (((x) >> 3) & 0x70))
#define STAGE   49152
#define SMEM_TOTAL (4 * STAGE)

// ---------------- gate: Wg cached in smem, fused x->fp16 ----------------
// 128 blocks x 256 threads; block covers 32 tokens (4 per warp).
__global__ void gate_kernel(const float* __restrict__ x, const float* __restrict__ Wg) {
    __shared__ float wgT[NE][DIMD];   // 32 KB transposed
    const int tid = threadIdx.x;
    const int wid = tid >> 5, lane = tid & 31;

    for (int idx = tid; idx < NE * DIMD; idx += 256) {
        int d = idx >> 3, e = idx & 7;
        wgT[e][d] = Wg[idx];
    }
    __syncthreads();

#pragma unroll 1
    for (int t = 0; t < 4; t++) {
        const int n = blockIdx.x * 32 + wid * 4 + t;
        const float* xr = x + (size_t)n * DIMD;
        __half2* xhr = (__half2*)(g_xh + (size_t)n * DIMD);

        float acc[NE];
#pragma unroll
        for (int e = 0; e < NE; e++) acc[e] = 0.f;
#pragma unroll
        for (int i = 0; i < DIMD / 64; i++) {
            int d = 64 * i + 2 * lane;
            float2 xv = *(const float2*)(xr + d);
            xhr[d >> 1] = __floats2half2_rn(xv.x, xv.y);
#pragma unroll
            for (int e = 0; e < NE; e++)
                acc[e] += xv.x * wgT[e][d] + xv.y * wgT[e][d + 1];
        }
#pragma unroll
        for (int e = 0; e < NE; e++) {
#pragma unroll
            for (int s = 16; s > 0; s >>= 1)
                acc[e] += __shfl_xor_sync(0xFFFFFFFFu, acc[e], s);
        }
        if (lane == 0) {
            float v[NE];
#pragma unroll
            for (int e = 0; e < NE; e++) v[e] = fmaxf(acc[e], 0.f);
            int e0 = 0; float p0 = v[0];
            int e1 = -1; float p1 = -1.f;
#pragma unroll
            for (int e = 1; e < NE; e++) {
                if (v[e] > p0)      { p1 = p0; e1 = e0; p0 = v[e]; e0 = e; }
                else if (v[e] > p1) { p1 = v[e]; e1 = e; }
            }
            float w0 = 1.f / (1.f + expf(p1 - p0));
            g_sel[2*n] = e0; g_sel[2*n+1] = e1;
            g_w[2*n] = w0;   g_w[2*n+1] = 1.f - w0;
        }
    }
}

// ---------------- plan: scan-based ranking, conflict-free LDS ----------------
__global__ void plan_kernel() {
    __shared__ int cnt_s[NE][1024];
    __shared__ int off_s[NE], tot_s[NE];
    const int tid = threadIdx.x;
    const int wid = tid >> 5, lane = tid & 31;

    int sel8[8];
    int c[NE];
#pragma unroll
    for (int e = 0; e < NE; e++) c[e] = 0;
#pragma unroll
    for (int j = 0; j < 8; j++) {
        sel8[j] = g_sel[tid * 8 + j];
        c[sel8[j]]++;
    }
#pragma unroll
    for (int e = 0; e < NE; e++) cnt_s[e][tid] = c[e];
    __syncthreads();

    // warp wid scans expert wid; lane touches threads {lane+32j} -> bank = lane (conflict-free)
    if (wid < NE) {
        int v[32];
        int s = 0;
#pragma unroll
        for (int j = 0; j < 32; j++) { v[j] = cnt_s[wid][lane + 32 * j]; s += v[j]; }
        int incl = s;
#pragma unroll
        for (int d = 1; d < 32; d <<= 1) {
            int t = __shfl_up_sync(0xFFFFFFFFu, incl, d);
            if (lane >= d) incl += t;
        }
        int run = incl - s;
        if (lane == 31) tot_s[wid] = incl;
#pragma unroll
        for (int j = 0; j < 32; j++) { cnt_s[wid][lane + 32 * j] = run; run += v[j]; }
    }
    __syncthreads();
    if (tid == 0) {
        int o = 0;
        for (int e = 0; e < NE; e++) {
            off_s[e] = o; g_off[e] = o; g_cnt[e] = tot_s[e]; o += tot_s[e];
        }
    }
    __syncthreads();

    int pref[NE];
#pragma unroll
    for (int e = 0; e < NE; e++) pref[e] = off_s[e] + cnt_s[e][tid];
#pragma unroll
    for (int j = 0; j < 8; j++) {
        int i = tid * 8 + j;
        int e = sel8[j];
        int r = pref[e]++;
        g_perm[r]   = i >> 1;
        g_wgt[r]    = g_w[i];
        g_rowpos[i] = r;
    }
}

// ---------------- weight converts: one float4 per thread ----------------
// conv1 half: 4 experts (4*1024*4096/4 = 4M float4 -> 16384 blocks)
__global__ void convert1h_kernel(const float4* __restrict__ src, int e0) {
    const size_t off = (size_t)e0 * DIMD * HID / 4;
    int i = blockIdx.x * 256 + threadIdx.x;
    float4 v = src[off + i];
    __half2* dst = (__half2*)g_w1h + 2 * (off + i);
    dst[0] = __floats2half2_rn(v.x, v.y);
    dst[1] = __floats2half2_rn(v.z, v.w);
}
// conv2: all 8 experts (8M float4 -> 32768 blocks)
__global__ void convert2_kernel(const float4* __restrict__ src) {
    int i = blockIdx.x * 256 + threadIdx.x;
    float4 v = src[i];
    __half2* dst = (__half2*)g_w2h + 2 * (size_t)i;
    dst[0] = __floats2half2_rn(v.x, v.y);
    dst[1] = __floats2half2_rn(v.z, v.w);
}

// ---------------- fp16 HMMA GEMM ----------------
// FIRST: A = g_xh via g_perm, C = g_hh (fp16). !FIRST: A = g_hh, C = g_yh (fp16).
template<int KD, int ND, bool FIRST>
__global__ __launch_bounds__(256, 1)
void gemm_hmma(const float* __restrict__ biasBase, int ebase)
{
    extern __shared__ __align__(128) char smem[];
    const int e    = blockIdx.z + ebase;
    const int cnt  = g_cnt[e];
    const int row0 = blockIdx.x * 128;
    if (row0 >= cnt) return;
    const int base = g_off[e];
    const int col0 = blockIdx.y * 256;

    const __half* Asrc = FIRST ? g_xh : g_hh;
    const __half* B    = (FIRST ? g_w1h : g_w2h) + (size_t)e * KD * ND + col0;
    const float*  bias = biasBase + (size_t)e * ND + col0;

    const uint32_t sb  = smem_u32(smem);
    const int tid = threadIdx.x;
    const int wid = tid >> 5, lane = tid & 31;
    const int wm = wid >> 2, wn = wid & 3;
    const int lq = lane >> 2, lr = lane & 3;
    const int ls = lane & 7;

    int aoff[4];
#pragma unroll
    for (int i = 0; i < 4; i++) {
        int r  = (tid >> 3) + 32 * i;
        int gr = row0 + r;
        int cr = (gr < cnt) ? gr : 0;
        aoff[i] = (FIRST ? g_perm[base + cr] : (base + cr)) * KD;
    }
    const int aj = tid & 7;
    const int bc = tid & 31;
    const int bkl = tid >> 5;

    auto fill = [&](int kt) {
        char* st = smem + (size_t)(kt & 3) * STAGE;
#pragma unroll
        for (int i = 0; i < 4; i++) {
            int r = (tid >> 3) + 32 * i;
            cp16(st + SW128(r * 128 + aj * 16), Asrc + aoff[i] + kt * 64 + aj * 8);
        }
#pragma unroll
        for (int i = 0; i < 8; i++) {
            int k = bkl + 8 * i;
            cp16(st + 16384 + k * 512 + ((bc ^ bkl) << 4),
                 B + (size_t)(kt * 64 + k) * ND + bc * 8);
        }
        asm volatile("cp.async.commit_group;");
    };

    const int KT = KD / 64;
    fill(0); fill(1); fill(2);

    float acc[4][8][4];
#pragma unroll
    for (int f = 0; f < 4; f++)
#pragma unroll
        for (int g = 0; g < 8; g++)
#pragma unroll
            for (int q = 0; q < 4; q++) acc[f][g][q] = 0.f;

    const uint32_t aRowB = (uint32_t)(wm * 64 + ((lane >> 3) & 1) * 8 + ls) * 128;
    const uint32_t aCh   = (uint32_t)(lane >> 4);
    const uint32_t bRowB = (uint32_t)(((lane >> 3) & 1) * 8 + ls) * 512;
    const uint32_t bC0   = (uint32_t)(wn * 8 + (lane >> 4));

#pragma unroll 1
    for (int kt = 0; kt < KT; kt++) {
        const int rem = KT - 1 - kt;
        if (rem >= 2)      asm volatile("cp.async.wait_group 2;");
        else if (rem == 1) asm volatile("cp.async.wait_group 1;");
        else               asm volatile("cp.async.wait_group 0;");
        __syncthreads();
        if (kt + 3 < KT) fill(kt + 3);

        const uint32_t sA = sb + (uint32_t)(kt & 3) * STAGE;
        const uint32_t sB = sA + 16384;
#pragma unroll
        for (int ks = 0; ks < 4; ks++) {
            uint32_t a[4][4], b[4][4];
#pragma unroll
            for (int f = 0; f < 4; f++)
                ldm4(a[f], sA + aRowB + f * 2048 + (((2 * ks + aCh) ^ ls) << 4));
#pragma unroll
            for (int p = 0; p < 4; p++)
                ldm4t(b[p], sB + ks * 8192 + bRowB + (((bC0 + 2 * p) ^ ls) << 4));
#pragma unroll
            for (int f = 0; f < 4; f++)
#pragma unroll
                for (int g = 0; g < 8; g++)
                    mma16816(acc[f][g], a[f], &b[g >> 1][(g & 1) * 2]);
        }
    }

    // ---- epilogue: bias + relu + fp16 stores ----
#pragma unroll
    for (int f = 0; f < 4; f++) {
        const int r0 = row0 + wm * 64 + f * 16 + lq;
        const int r1 = r0 + 8;
#pragma unroll
        for (int g = 0; g < 8; g++) {
            const int col = wn * 64 + g * 8 + 2 * lr;
            float2 bb = *(const float2*)(bias + col);
            float v00 = fmaxf(acc[f][g][0] + bb.x, 0.f);
            float v01 = fmaxf(acc[f][g][1] + bb.y, 0.f);
            float v10 = fmaxf(acc[f][g][2] + bb.x, 0.f);
            float v11 = fmaxf(acc[f][g][3] + bb.y, 0.f);
            __half* C = FIRST ? g_hh : g_yh;
            if (r0 < cnt)
                *(__half2*)(C + (size_t)(base + r0) * ND + col0 + col) = __floats2half2_rn(v00, v01);
            if (r1 < cnt)
                *(__half2*)(C + (size_t)(base + r1) * ND + col0 + col) = __floats2half2_rn(v10, v11);
        }
    }
}

// ---------------- combine (fp16 y inputs, fp32 out) ----------------
__global__ void combine_kernel(float* __restrict__ out) {
    int gid = blockIdx.x * blockDim.x + threadIdx.x;
    if (gid >= N_TOK * OUTD / 4) return;
    int n = gid / (OUTD / 4);
    int c = (gid % (OUTD / 4)) * 4;
    int r0 = g_rowpos[2*n], r1 = g_rowpos[2*n + 1];
    float w0 = g_wgt[r0], w1 = g_wgt[r1];
    const __half2* y0p = (const __half2*)(g_yh + (size_t)r0 * OUTD + c);
    const __half2* y1p = (const __half2*)(g_yh + (size_t)r1 * OUTD + c);
    float2 a0 = __half22float2(y0p[0]), a1 = __half22float2(y0p[1]);
    float2 b0 = __half22float2(y1p[0]), b1 = __half22float2(y1p[1]);
    float4 o;
    o.x = w0*a0.x + w1*b0.x;
    o.y = w0*a0.y + w1*b0.y;
    o.z = w0*a1.x + w1*b1.x;
    o.w = w0*a1.y + w1*b1.y;
    *(float4*)(out + (size_t)n * OUTD + c) = o;
}

// ---------------- launch ----------------
extern "C" void kernel_launch(void* const* d_in, const int* in_sizes, int n_in,
                              void* d_out, int out_size) {
    const float* x  = (const float*)d_in[0];
    const float* Wg = (const float*)d_in[1];
    const float* W1 = (const float*)d_in[2];
    const float* b1 = (const float*)d_in[3];
    const float* W2 = (const float*)d_in[4];
    const float* b2 = (const float*)d_in[5];
    float* out = (float*)d_out;

    static cudaStream_t s1 = nullptr;
    static cudaEvent_t evFork = nullptr, evC1a = nullptr, evC1b = nullptr, evC2 = nullptr;
    static bool inited = false;
    if (!inited) {
        cudaStreamCreateWithFlags(&s1, cudaStreamNonBlocking);
        cudaEventCreateWithFlags(&evFork, cudaEventDisableTiming);
        cudaEventCreateWithFlags(&evC1a, cudaEventDisableTiming);
        cudaEventCreateWithFlags(&evC1b, cudaEventDisableTiming);
        cudaEventCreateWithFlags(&evC2,  cudaEventDisableTiming);
        cudaFuncSetAttribute(gemm_hmma<DIMD, HID, true>,
                             cudaFuncAttributeMaxDynamicSharedMemorySize, SMEM_TOTAL);
        cudaFuncSetAttribute(gemm_hmma<HID, OUTD, false>,
                             cudaFuncAttributeMaxDynamicSharedMemorySize, SMEM_TOTAL);
        inited = true;
    }

    // fork: weight converts on side stream (experts 0-3, then 4-7, then W2)
    cudaEventRecord(evFork, 0);
    cudaStreamWaitEvent(s1, evFork, 0);
    convert1h_kernel<<<16384, 256, 0, s1>>>((const float4*)W1, 0);
    cudaEventRecord(evC1a, s1);
    convert1h_kernel<<<16384, 256, 0, s1>>>((const float4*)W1, 4);
    cudaEventRecord(evC1b, s1);
    convert2_kernel<<<32768, 256, 0, s1>>>((const float4*)W2);
    cudaEventRecord(evC2, s1);

    // main: gate (smem Wg) + plan
    gate_kernel<<<N_TOK / 32, 256>>>(x, Wg);
    plan_kernel<<<1, 1024>>>();

    // GEMM1 experts 0-3 after first conv half; 4-7 after second
    cudaStreamWaitEvent(0, evC1a, 0);
    {
        dim3 grid(RMAX / 128, HID / 256, 4);
        gemm_hmma<DIMD, HID, true><<<grid, 256, SMEM_TOTAL>>>(b1, 0);
    }
    cudaStreamWaitEvent(0, evC1b, 0);
    {
        dim3 grid(RMAX / 128, HID / 256, 4);
        gemm_hmma<DIMD, HID, true><<<grid, 256, SMEM_TOTAL>>>(b1, 4);
    }
    // GEMM2 after W2 convert
    cudaStreamWaitEvent(0, evC2, 0);
    {
        dim3 grid(RMAX / 128, OUTD / 256, NE);
        gemm_hmma<HID, OUTD, false><<<grid, 256, SMEM_TOTAL>>>(b2, 0);
    }
    combine_kernel<<<(N_TOK * OUTD / 4 + 255) / 256, 256>>>(out);
}

// round 13
// speedup vs baseline: 1.0099x; 1.0099x over previous
#include <cuda_runtime.h>
#include <cuda_fp16.h>
#include <math.h>
#include <stdint.h>

#define N_TOK 4096
#define DIMD  1024
#define HID   4096
#define OUTD  1024
#define NE    8
#define RMAX  (2*N_TOK)

// ---------------- scratch (static device globals) ----------------
__device__ __half g_xh[(size_t)N_TOK * DIMD];      //  8 MB x fp16 (token order)
__device__ __half g_hh[(size_t)RMAX * HID];        // 64 MB GEMM1 out (fp16, expert-sorted)
__device__ __half g_yh[(size_t)RMAX * OUTD];       // 16 MB GEMM2 out (fp16)
__device__ __half g_w1h[(size_t)NE * DIMD * HID];  // 64 MB
__device__ __half g_w2h[(size_t)NE * HID * OUTD];  // 64 MB
__device__ int   g_perm[RMAX];
__device__ float g_wgt[RMAX];
__device__ int   g_rowpos[N_TOK * 2];
__device__ int   g_sel[N_TOK * 2];
__device__ float g_w[N_TOK * 2];
__device__ int   g_cnt[NE];
__device__ int   g_off[NE];

// ---------------- helpers ----------------
__device__ __forceinline__ void cp16(void* dst, const void* src) {
    unsigned sd = (unsigned)__cvta_generic_to_shared(dst);
    asm volatile("cp.async.cg.shared.global [%0], [%1], 16;" :: "r"(sd), "l"(src));
}
__device__ __forceinline__ uint32_t smem_u32(const void* p) {
    uint32_t a;
    asm("{ .reg .u64 t; cvta.to.shared.u64 t, %1; cvt.u32.u64 %0, t; }" : "=r"(a) : "l"(p));
    return a;
}
__device__ __forceinline__ void ldm4(uint32_t r[4], uint32_t addr) {
    asm volatile("ldmatrix.sync.aligned.m8n8.x4.shared.b16 {%0,%1,%2,%3}, [%4];"
        : "=r"(r[0]), "=r"(r[1]), "=r"(r[2]), "=r"(r[3]) : "r"(addr));
}
__device__ __forceinline__ void ldm4t(uint32_t r[4], uint32_t addr) {
    asm volatile("ldmatrix.sync.aligned.m8n8.x4.trans.shared.b16 {%0,%1,%2,%3}, [%4];"
        : "=r"(r[0]), "=r"(r[1]), "=r"(r[2]), "=r"(r[3]) : "r"(addr));
}
__device__ __forceinline__ void mma16816(float c[4], const uint32_t a[4], const uint32_t* b) {
    asm volatile("mma.sync.aligned.m16n8k16.row.col.f32.f16.f16.f32 "
        "{%0,%1,%2,%3}, {%4,%5,%6,%7}, {%8,%9}, {%0,%1,%2,%3};"
        : "+f"(c[0]), "+f"(c[1]), "+f"(c[2]), "+f"(c[3])
        : "r"(a[0]), "r"(a[1]), "r"(a[2]), "r"(a[3]), "r"(b[0]), "r"(b[1]));
}

#define SW128(x) ((x) ^ (((x) >> 3) & 0x70))
#define STAGE   49152
#define SMEM_TOTAL (4 * STAGE)

// ---------------- gate: Wg in smem, fused x->fp16, reg-capped ----------------
// 128 blocks x 256 threads; block covers 32 tokens (4 per warp, serial).
__global__ __launch_bounds__(256, 2)
void gate_kernel(const float* __restrict__ x, const float* __restrict__ Wg) {
    __shared__ float wgT[NE][DIMD];   // 32 KB transposed
    const int tid = threadIdx.x;
    const int wid = tid >> 5, lane = tid & 31;

    for (int idx = tid; idx < NE * DIMD; idx += 256) {
        int d = idx >> 3, e = idx & 7;
        wgT[e][d] = Wg[idx];
    }
    __syncthreads();

#pragma unroll 1
    for (int t = 0; t < 4; t++) {
        const int n = blockIdx.x * 32 + wid * 4 + t;
        const float* xr = x + (size_t)n * DIMD;
        __half2* xhr = (__half2*)(g_xh + (size_t)n * DIMD);

        float acc[NE];
#pragma unroll
        for (int e = 0; e < NE; e++) acc[e] = 0.f;
#pragma unroll 4
        for (int i = 0; i < DIMD / 64; i++) {
            int d = 64 * i + 2 * lane;
            float2 xv = *(const float2*)(xr + d);
            xhr[d >> 1] = __floats2half2_rn(xv.x, xv.y);
#pragma unroll
            for (int e = 0; e < NE; e++)
                acc[e] += xv.x * wgT[e][d] + xv.y * wgT[e][d + 1];
        }
#pragma unroll
        for (int e = 0; e < NE; e++) {
#pragma unroll
            for (int s = 16; s > 0; s >>= 1)
                acc[e] += __shfl_xor_sync(0xFFFFFFFFu, acc[e], s);
        }
        if (lane == 0) {
            float v[NE];
#pragma unroll
            for (int e = 0; e < NE; e++) v[e] = fmaxf(acc[e], 0.f);
            int e0 = 0; float p0 = v[0];
            int e1 = -1; float p1 = -1.f;
#pragma unroll
            for (int e = 1; e < NE; e++) {
                if (v[e] > p0)      { p1 = p0; e1 = e0; p0 = v[e]; e0 = e; }
                else if (v[e] > p1) { p1 = v[e]; e1 = e; }
            }
            float w0 = 1.f / (1.f + expf(p1 - p0));
            g_sel[2*n] = e0; g_sel[2*n+1] = e1;
            g_w[2*n] = w0;   g_w[2*n+1] = 1.f - w0;
        }
    }
}

// ---------------- plan: scan-based ranking, conflict-free LDS ----------------
__global__ void plan_kernel() {
    __shared__ int cnt_s[NE][1024];
    __shared__ int off_s[NE], tot_s[NE];
    const int tid = threadIdx.x;
    const int wid = tid >> 5, lane = tid & 31;

    int sel8[8];
    int c[NE];
#pragma unroll
    for (int e = 0; e < NE; e++) c[e] = 0;
#pragma unroll
    for (int j = 0; j < 8; j++) {
        sel8[j] = g_sel[tid * 8 + j];
        c[sel8[j]]++;
    }
#pragma unroll
    for (int e = 0; e < NE; e++) cnt_s[e][tid] = c[e];
    __syncthreads();

    // warp wid scans expert wid; lane touches threads {lane+32j} -> bank = lane (conflict-free)
    if (wid < NE) {
        int v[32];
        int s = 0;
#pragma unroll
        for (int j = 0; j < 32; j++) { v[j] = cnt_s[wid][lane + 32 * j]; s += v[j]; }
        int incl = s;
#pragma unroll
        for (int d = 1; d < 32; d <<= 1) {
            int t = __shfl_up_sync(0xFFFFFFFFu, incl, d);
            if (lane >= d) incl += t;
        }
        int run = incl - s;
        if (lane == 31) tot_s[wid] = incl;
#pragma unroll
        for (int j = 0; j < 32; j++) { cnt_s[wid][lane + 32 * j] = run; run += v[j]; }
    }
    __syncthreads();
    if (tid == 0) {
        int o = 0;
        for (int e = 0; e < NE; e++) {
            off_s[e] = o; g_off[e] = o; g_cnt[e] = tot_s[e]; o += tot_s[e];
        }
    }
    __syncthreads();

    int pref[NE];
#pragma unroll
    for (int e = 0; e < NE; e++) pref[e] = off_s[e] + cnt_s[e][tid];
#pragma unroll
    for (int j = 0; j < 8; j++) {
        int i = tid * 8 + j;
        int e = sel8[j];
        int r = pref[e]++;
        g_perm[r]   = i >> 1;
        g_wgt[r]    = g_w[i];
        g_rowpos[i] = r;
    }
}

// ---------------- weight converts: one float4 per thread, one-shot ----------------
__global__ void convert1_kernel(const float4* __restrict__ src) {
    size_t i = (size_t)blockIdx.x * 256 + threadIdx.x;   // 8M float4
    float4 v = src[i];
    __half2* dst = (__half2*)g_w1h + 2 * i;
    dst[0] = __floats2half2_rn(v.x, v.y);
    dst[1] = __floats2half2_rn(v.z, v.w);
}
__global__ void convert2_kernel(const float4* __restrict__ src) {
    size_t i = (size_t)blockIdx.x * 256 + threadIdx.x;   // 8M float4
    float4 v = src[i];
    __half2* dst = (__half2*)g_w2h + 2 * i;
    dst[0] = __floats2half2_rn(v.x, v.y);
    dst[1] = __floats2half2_rn(v.z, v.w);
}

// ---------------- fp16 HMMA GEMM ----------------
// FIRST: A = g_xh via g_perm, C = g_hh (fp16). !FIRST: A = g_hh, C = g_yh (fp16).
template<int KD, int ND, bool FIRST>
__global__ __launch_bounds__(256, 1)
void gemm_hmma(const float* __restrict__ biasBase)
{
    extern __shared__ __align__(128) char smem[];
    const int e    = blockIdx.z;
    const int cnt  = g_cnt[e];
    const int row0 = blockIdx.x * 128;
    if (row0 >= cnt) return;
    const int base = g_off[e];
    const int col0 = blockIdx.y * 256;

    const __half* Asrc = FIRST ? g_xh : g_hh;
    const __half* B    = (FIRST ? g_w1h : g_w2h) + (size_t)e * KD * ND + col0;
    const float*  bias = biasBase + (size_t)e * ND + col0;

    const uint32_t sb  = smem_u32(smem);
    const int tid = threadIdx.x;
    const int wid = tid >> 5, lane = tid & 31;
    const int wm = wid >> 2, wn = wid & 3;
    const int lq = lane >> 2, lr = lane & 3;
    const int ls = lane & 7;

    int aoff[4];
#pragma unroll
    for (int i = 0; i < 4; i++) {
        int r  = (tid >> 3) + 32 * i;
        int gr = row0 + r;
        int cr = (gr < cnt) ? gr : 0;
        aoff[i] = (FIRST ? g_perm[base + cr] : (base + cr)) * KD;
    }
    const int aj = tid & 7;
    const int bc = tid & 31;
    const int bkl = tid >> 5;

    auto fill = [&](int kt) {
        char* st = smem + (size_t)(kt & 3) * STAGE;
#pragma unroll
        for (int i = 0; i < 4; i++) {
            int r = (tid >> 3) + 32 * i;
            cp16(st + SW128(r * 128 + aj * 16), Asrc + aoff[i] + kt * 64 + aj * 8);
        }
#pragma unroll
        for (int i = 0; i < 8; i++) {
            int k = bkl + 8 * i;
            cp16(st + 16384 + k * 512 + ((bc ^ bkl) << 4),
                 B + (size_t)(kt * 64 + k) * ND + bc * 8);
        }
        asm volatile("cp.async.commit_group;");
    };

    const int KT = KD / 64;
    fill(0); fill(1); fill(2);

    float acc[4][8][4];
#pragma unroll
    for (int f = 0; f < 4; f++)
#pragma unroll
        for (int g = 0; g < 8; g++)
#pragma unroll
            for (int q = 0; q < 4; q++) acc[f][g][q] = 0.f;

    const uint32_t aRowB = (uint32_t)(wm * 64 + ((lane >> 3) & 1) * 8 + ls) * 128;
    const uint32_t aCh   = (uint32_t)(lane >> 4);
    const uint32_t bRowB = (uint32_t)(((lane >> 3) & 1) * 8 + ls) * 512;
    const uint32_t bC0   = (uint32_t)(wn * 8 + (lane >> 4));

#pragma unroll 1
    for (int kt = 0; kt < KT; kt++) {
        const int rem = KT - 1 - kt;
        if (rem >= 2)      asm volatile("cp.async.wait_group 2;");
        else if (rem == 1) asm volatile("cp.async.wait_group 1;");
        else               asm volatile("cp.async.wait_group 0;");
        __syncthreads();
        if (kt + 3 < KT) fill(kt + 3);

        const uint32_t sA = sb + (uint32_t)(kt & 3) * STAGE;
        const uint32_t sB = sA + 16384;
#pragma unroll
        for (int ks = 0; ks < 4; ks++) {
            uint32_t a[4][4], b[4][4];
#pragma unroll
            for (int f = 0; f < 4; f++)
                ldm4(a[f], sA + aRowB + f * 2048 + (((2 * ks + aCh) ^ ls) << 4));
#pragma unroll
            for (int p = 0; p < 4; p++)
                ldm4t(b[p], sB + ks * 8192 + bRowB + (((bC0 + 2 * p) ^ ls) << 4));
#pragma unroll
            for (int f = 0; f < 4; f++)
#pragma unroll
                for (int g = 0; g < 8; g++)
                    mma16816(acc[f][g], a[f], &b[g >> 1][(g & 1) * 2]);
        }
    }

    // ---- epilogue: bias + relu + fp16 stores ----
#pragma unroll
    for (int f = 0; f < 4; f++) {
        const int r0 = row0 + wm * 64 + f * 16 + lq;
        const int r1 = r0 + 8;
#pragma unroll
        for (int g = 0; g < 8; g++) {
            const int col = wn * 64 + g * 8 + 2 * lr;
            float2 bb = *(const float2*)(bias + col);
            float v00 = fmaxf(acc[f][g][0] + bb.x, 0.f);
            float v01 = fmaxf(acc[f][g][1] + bb.y, 0.f);
            float v10 = fmaxf(acc[f][g][2] + bb.x, 0.f);
            float v11 = fmaxf(acc[f][g][3] + bb.y, 0.f);
            __half* C = FIRST ? g_hh : g_yh;
            if (r0 < cnt)
                *(__half2*)(C + (size_t)(base + r0) * ND + col0 + col) = __floats2half2_rn(v00, v01);
            if (r1 < cnt)
                *(__half2*)(C + (size_t)(base + r1) * ND + col0 + col) = __floats2half2_rn(v10, v11);
        }
    }
}

// ---------------- combine (fp16 y inputs, fp32 out) ----------------
__global__ void combine_kernel(float* __restrict__ out) {
    int gid = blockIdx.x * blockDim.x + threadIdx.x;
    if (gid >= N_TOK * OUTD / 4) return;
    int n = gid / (OUTD / 4);
    int c = (gid % (OUTD / 4)) * 4;
    int r0 = g_rowpos[2*n], r1 = g_rowpos[2*n + 1];
    float w0 = g_wgt[r0], w1 = g_wgt[r1];
    const __half2* y0p = (const __half2*)(g_yh + (size_t)r0 * OUTD + c);
    const __half2* y1p = (const __half2*)(g_yh + (size_t)r1 * OUTD + c);
    float2 a0 = __half22float2(y0p[0]), a1 = __half22float2(y0p[1]);
    float2 b0 = __half22float2(y1p[0]), b1 = __half22float2(y1p[1]);
    float4 o;
    o.x = w0*a0.x + w1*b0.x;
    o.y = w0*a0.y + w1*b0.y;
    o.z = w0*a1.x + w1*b1.x;
    o.w = w0*a1.y + w1*b1.y;
    *(float4*)(out + (size_t)n * OUTD + c) = o;
}

// ---------------- launch ----------------
extern "C" void kernel_launch(void* const* d_in, const int* in_sizes, int n_in,
                              void* d_out, int out_size) {
    const float* x  = (const float*)d_in[0];
    const float* Wg = (const float*)d_in[1];
    const float* W1 = (const float*)d_in[2];
    const float* b1 = (const float*)d_in[3];
    const float* W2 = (const float*)d_in[4];
    const float* b2 = (const float*)d_in[5];
    float* out = (float*)d_out;

    static cudaStream_t s1 = nullptr;
    static cudaEvent_t evFork = nullptr, evC1 = nullptr, evC2 = nullptr;
    static bool inited = false;
    if (!inited) {
        cudaStreamCreateWithFlags(&s1, cudaStreamNonBlocking);
        cudaEventCreateWithFlags(&evFork, cudaEventDisableTiming);
        cudaEventCreateWithFlags(&evC1,  cudaEventDisableTiming);
        cudaEventCreateWithFlags(&evC2,  cudaEventDisableTiming);
        cudaFuncSetAttribute(gemm_hmma<DIMD, HID, true>,
                             cudaFuncAttributeMaxDynamicSharedMemorySize, SMEM_TOTAL);
        cudaFuncSetAttribute(gemm_hmma<HID, OUTD, false>,
                             cudaFuncAttributeMaxDynamicSharedMemorySize, SMEM_TOTAL);
        inited = true;
    }

    // fork: weight converts on side stream (one-shot grids)
    cudaEventRecord(evFork, 0);
    cudaStreamWaitEvent(s1, evFork, 0);
    convert1_kernel<<<NE * DIMD * HID / 1024, 256, 0, s1>>>((const float4*)W1);
    cudaEventRecord(evC1, s1);
    convert2_kernel<<<NE * HID * OUTD / 1024, 256, 0, s1>>>((const float4*)W2);
    cudaEventRecord(evC2, s1);

    // main: gate (smem Wg, reg-capped) + plan
    gate_kernel<<<N_TOK / 32, 256>>>(x, Wg);
    plan_kernel<<<1, 1024>>>();

    // GEMM1 (single launch, all experts)
    cudaStreamWaitEvent(0, evC1, 0);
    {
        dim3 grid(RMAX / 128, HID / 256, NE);
        gemm_hmma<DIMD, HID, true><<<grid, 256, SMEM_TOTAL>>>(b1);
    }
    // GEMM2
    cudaStreamWaitEvent(0, evC2, 0);
    {
        dim3 grid(RMAX / 128, OUTD / 256, NE);
        gemm_hmma<HID, OUTD, false><<<grid, 256, SMEM_TOTAL>>>(b2);
    }
    combine_kernel<<<(N_TOK * OUTD / 4 + 255) / 256, 256>>>(out);
}

// round 14
// speedup vs baseline: 1.0444x; 1.0342x over previous
#include <cuda_runtime.h>
#include <cuda_fp16.h>
#include <math.h>
#include <stdint.h>

#define N_TOK 4096
#define DIMD  1024
#define HID   4096
#define OUTD  1024
#define NE    8
#define RMAX  (2*N_TOK)

// ---------------- scratch (static device globals) ----------------
__device__ __half g_xh[(size_t)N_TOK * DIMD];      //  8 MB x fp16 (token order)
__device__ __half g_hh[(size_t)RMAX * HID];        // 64 MB GEMM1 out (fp16, expert-sorted)
__device__ __half g_yh[(size_t)RMAX * OUTD];       // 16 MB GEMM2 out (fp16)
__device__ __half g_w1h[(size_t)NE * DIMD * HID];  // 64 MB
__device__ __half g_w2h[(size_t)NE * HID * OUTD];  // 64 MB
__device__ int   g_perm[RMAX];
__device__ float g_wgt[RMAX];
__device__ int   g_rowpos[N_TOK * 2];
__device__ int   g_sel[N_TOK * 2];
__device__ float g_w[N_TOK * 2];
__device__ int   g_cnt[NE];
__device__ int   g_off[NE];

// ---------------- helpers ----------------
__device__ __forceinline__ void cp16(void* dst, const void* src) {
    unsigned sd = (unsigned)__cvta_generic_to_shared(dst);
    asm volatile("cp.async.cg.shared.global [%0], [%1], 16;" :: "r"(sd), "l"(src));
}
__device__ __forceinline__ uint32_t smem_u32(const void* p) {
    uint32_t a;
    asm("{ .reg .u64 t; cvta.to.shared.u64 t, %1; cvt.u32.u64 %0, t; }" : "=r"(a) : "l"(p));
    return a;
}
__device__ __forceinline__ void ldm4(uint32_t r[4], uint32_t addr) {
    asm volatile("ldmatrix.sync.aligned.m8n8.x4.shared.b16 {%0,%1,%2,%3}, [%4];"
        : "=r"(r[0]), "=r"(r[1]), "=r"(r[2]), "=r"(r[3]) : "r"(addr));
}
__device__ __forceinline__ void ldm4t(uint32_t r[4], uint32_t addr) {
    asm volatile("ldmatrix.sync.aligned.m8n8.x4.trans.shared.b16 {%0,%1,%2,%3}, [%4];"
        : "=r"(r[0]), "=r"(r[1]), "=r"(r[2]), "=r"(r[3]) : "r"(addr));
}
__device__ __forceinline__ void mma16816(float c[4], const uint32_t a[4], const uint32_t* b) {
    asm volatile("mma.sync.aligned.m16n8k16.row.col.f32.f16.f16.f32 "
        "{%0,%1,%2,%3}, {%4,%5,%6,%7}, {%8,%9}, {%0,%1,%2,%3};"
        : "+f"(c[0]), "+f"(c[1]), "+f"(c[2]), "+f"(c[3])
        : "r"(a[0]), "r"(a[1]), "r"(a[2]), "r"(a[3]), "r"(b[0]), "r"(b[1]));
}

#define SW128(x) ((x) ^ (((x) >> 3) & 0x70))
#define STAGE   49152
#define SMEM_TOTAL (4 * STAGE)

// ---------------- gate: Wg in smem, fused x->fp16, reg-capped ----------------
__global__ __launch_bounds__(256, 2)
void gate_kernel(const float* __restrict__ x, const float* __restrict__ Wg) {
    __shared__ float wgT[NE][DIMD];
    const int tid = threadIdx.x;
    const int wid = tid >> 5, lane = tid & 31;

    for (int idx = tid; idx < NE * DIMD; idx += 256) {
        int d = idx >> 3, e = idx & 7;
        wgT[e][d] = Wg[idx];
    }
    __syncthreads();

#pragma unroll 1
    for (int t = 0; t < 4; t++) {
        const int n = blockIdx.x * 32 + wid * 4 + t;
        const float* xr = x + (size_t)n * DIMD;
        __half2* xhr = (__half2*)(g_xh + (size_t)n * DIMD);

        float acc[NE];
#pragma unroll
        for (int e = 0; e < NE; e++) acc[e] = 0.f;
#pragma unroll 4
        for (int i = 0; i < DIMD / 64; i++) {
            int d = 64 * i + 2 * lane;
            float2 xv = *(const float2*)(xr + d);
            xhr[d >> 1] = __floats2half2_rn(xv.x, xv.y);
#pragma unroll
            for (int e = 0; e < NE; e++)
                acc[e] += xv.x * wgT[e][d] + xv.y * wgT[e][d + 1];
        }
#pragma unroll
        for (int e = 0; e < NE; e++) {
#pragma unroll
            for (int s = 16; s > 0; s >>= 1)
                acc[e] += __shfl_xor_sync(0xFFFFFFFFu, acc[e], s);
        }
        if (lane == 0) {
            float v[NE];
#pragma unroll
            for (int e = 0; e < NE; e++) v[e] = fmaxf(acc[e], 0.f);
            int e0 = 0; float p0 = v[0];
            int e1 = -1; float p1 = -1.f;
#pragma unroll
            for (int e = 1; e < NE; e++) {
                if (v[e] > p0)      { p1 = p0; e1 = e0; p0 = v[e]; e0 = e; }
                else if (v[e] > p1) { p1 = v[e]; e1 = e; }
            }
            float w0 = 1.f / (1.f + expf(p1 - p0));
            g_sel[2*n] = e0; g_sel[2*n+1] = e1;
            g_w[2*n] = w0;   g_w[2*n+1] = 1.f - w0;
        }
    }
}

// ---------------- plan: 8-block count + 8-block stable scatter ----------------
__global__ void plan_count_kernel() {
    __shared__ int red[8];
    const int e = blockIdx.x, t = threadIdx.x;
    int c = 0;
#pragma unroll 8
    for (int j = 0; j < 32; j++) c += (g_sel[t + 256 * j] == e);
#pragma unroll
    for (int s = 16; s > 0; s >>= 1) c += __shfl_xor_sync(0xFFFFFFFFu, c, s);
    if ((t & 31) == 0) red[t >> 5] = c;
    __syncthreads();
    if (t == 0) {
        int s = 0;
        for (int w = 0; w < 8; w++) s += red[w];
        g_cnt[e] = s;
    }
}

__global__ void plan_scatter_kernel() {
    __shared__ int wsum[8];
    __shared__ int base_s;
    const int e = blockIdx.x, t = threadIdx.x;
    const int lane = t & 31, wd = t >> 5;

    if (t == 0) {
        int o = 0;
        for (int i = 0; i < e; i++) o += g_cnt[i];
        base_s = o;
        g_off[e] = o;
    }

    int sl[32];
    int c = 0;
#pragma unroll 8
    for (int j = 0; j < 32; j++) {
        sl[j] = g_sel[32 * t + j];
        c += (sl[j] == e);
    }
    int incl = c;
#pragma unroll
    for (int d = 1; d < 32; d <<= 1) {
        int v = __shfl_up_sync(0xFFFFFFFFu, incl, d);
        if (lane >= d) incl += v;
    }
    if (lane == 31) wsum[wd] = incl;
    __syncthreads();
    int wbase = 0;
    for (int w = 0; w < wd; w++) wbase += wsum[w];
    int r = base_s + wbase + incl - c;   // stable global rank start for this thread

#pragma unroll 8
    for (int j = 0; j < 32; j++) {
        int i = 32 * t + j;
        if (sl[j] == e) {
            g_perm[r]   = i >> 1;
            g_wgt[r]    = g_w[i];
            g_rowpos[i] = r;
            r++;
        }
    }
}

// ---------------- weight converts: one float4 per thread, one-shot ----------------
__global__ void convert1_kernel(const float4* __restrict__ src) {
    size_t i = (size_t)blockIdx.x * 256 + threadIdx.x;
    float4 v = src[i];
    __half2* dst = (__half2*)g_w1h + 2 * i;
    dst[0] = __floats2half2_rn(v.x, v.y);
    dst[1] = __floats2half2_rn(v.z, v.w);
}
__global__ void convert2_kernel(const float4* __restrict__ src) {
    size_t i = (size_t)blockIdx.x * 256 + threadIdx.x;
    float4 v = src[i];
    __half2* dst = (__half2*)g_w2h + 2 * i;
    dst[0] = __floats2half2_rn(v.x, v.y);
    dst[1] = __floats2half2_rn(v.z, v.w);
}

// ---------------- fp16 HMMA GEMM (ebase selects expert group) ----------------
template<int KD, int ND, bool FIRST>
__global__ __launch_bounds__(256, 1)
void gemm_hmma(const float* __restrict__ biasBase, int ebase)
{
    extern __shared__ __align__(128) char smem[];
    const int e    = blockIdx.z + ebase;
    const int cnt  = g_cnt[e];
    const int row0 = blockIdx.x * 128;
    if (row0 >= cnt) return;
    const int base = g_off[e];
    const int col0 = blockIdx.y * 256;

    const __half* Asrc = FIRST ? g_xh : g_hh;
    const __half* B    = (FIRST ? g_w1h : g_w2h) + (size_t)e * KD * ND + col0;
    const float*  bias = biasBase + (size_t)e * ND + col0;

    const uint32_t sb  = smem_u32(smem);
    const int tid = threadIdx.x;
    const int wid = tid >> 5, lane = tid & 31;
    const int wm = wid >> 2, wn = wid & 3;
    const int lq = lane >> 2, lr = lane & 3;
    const int ls = lane & 7;

    int aoff[4];
#pragma unroll
    for (int i = 0; i < 4; i++) {
        int r  = (tid >> 3) + 32 * i;
        int gr = row0 + r;
        int cr = (gr < cnt) ? gr : 0;
        aoff[i] = (FIRST ? g_perm[base + cr] : (base + cr)) * KD;
    }
    const int aj = tid & 7;
    const int bc = tid & 31;
    const int bkl = tid >> 5;

    auto fill = [&](int kt) {
        char* st = smem + (size_t)(kt & 3) * STAGE;
#pragma unroll
        for (int i = 0; i < 4; i++) {
            int r = (tid >> 3) + 32 * i;
            cp16(st + SW128(r * 128 + aj * 16), Asrc + aoff[i] + kt * 64 + aj * 8);
        }
#pragma unroll
        for (int i = 0; i < 8; i++) {
            int k = bkl + 8 * i;
            cp16(st + 16384 + k * 512 + ((bc ^ bkl) << 4),
                 B + (size_t)(kt * 64 + k) * ND + bc * 8);
        }
        asm volatile("cp.async.commit_group;");
    };

    const int KT = KD / 64;
    fill(0); fill(1); fill(2);

    float acc[4][8][4];
#pragma unroll
    for (int f = 0; f < 4; f++)
#pragma unroll
        for (int g = 0; g < 8; g++)
#pragma unroll
            for (int q = 0; q < 4; q++) acc[f][g][q] = 0.f;

    const uint32_t aRowB = (uint32_t)(wm * 64 + ((lane >> 3) & 1) * 8 + ls) * 128;
    const uint32_t aCh   = (uint32_t)(lane >> 4);
    const uint32_t bRowB = (uint32_t)(((lane >> 3) & 1) * 8 + ls) * 512;
    const uint32_t bC0   = (uint32_t)(wn * 8 + (lane >> 4));

#pragma unroll 1
    for (int kt = 0; kt < KT; kt++) {
        const int rem = KT - 1 - kt;
        if (rem >= 2)      asm volatile("cp.async.wait_group 2;");
        else if (rem == 1) asm volatile("cp.async.wait_group 1;");
        else               asm volatile("cp.async.wait_group 0;");
        __syncthreads();
        if (kt + 3 < KT) fill(kt + 3);

        const uint32_t sA = sb + (uint32_t)(kt & 3) * STAGE;
        const uint32_t sB = sA + 16384;
#pragma unroll
        for (int ks = 0; ks < 4; ks++) {
            uint32_t a[4][4], b[4][4];
#pragma unroll
            for (int f = 0; f < 4; f++)
                ldm4(a[f], sA + aRowB + f * 2048 + (((2 * ks + aCh) ^ ls) << 4));
#pragma unroll
            for (int p = 0; p < 4; p++)
                ldm4t(b[p], sB + ks * 8192 + bRowB + (((bC0 + 2 * p) ^ ls) << 4));
#pragma unroll
            for (int f = 0; f < 4; f++)
#pragma unroll
                for (int g = 0; g < 8; g++)
                    mma16816(acc[f][g], a[f], &b[g >> 1][(g & 1) * 2]);
        }
    }

    // ---- epilogue: bias + relu + fp16 stores ----
#pragma unroll
    for (int f = 0; f < 4; f++) {
        const int r0 = row0 + wm * 64 + f * 16 + lq;
        const int r1 = r0 + 8;
#pragma unroll
        for (int g = 0; g < 8; g++) {
            const int col = wn * 64 + g * 8 + 2 * lr;
            float2 bb = *(const float2*)(bias + col);
            float v00 = fmaxf(acc[f][g][0] + bb.x, 0.f);
            float v01 = fmaxf(acc[f][g][1] + bb.y, 0.f);
            float v10 = fmaxf(acc[f][g][2] + bb.x, 0.f);
            float v11 = fmaxf(acc[f][g][3] + bb.y, 0.f);
            __half* C = FIRST ? g_hh : g_yh;
            if (r0 < cnt)
                *(__half2*)(C + (size_t)(base + r0) * ND + col0 + col) = __floats2half2_rn(v00, v01);
            if (r1 < cnt)
                *(__half2*)(C + (size_t)(base + r1) * ND + col0 + col) = __floats2half2_rn(v10, v11);
        }
    }
}

// ---------------- combine (fp16 y inputs, fp32 out) ----------------
__global__ void combine_kernel(float* __restrict__ out) {
    int gid = blockIdx.x * blockDim.x + threadIdx.x;
    if (gid >= N_TOK * OUTD / 4) return;
    int n = gid / (OUTD / 4);
    int c = (gid % (OUTD / 4)) * 4;
    int r0 = g_rowpos[2*n], r1 = g_rowpos[2*n + 1];
    float w0 = g_wgt[r0], w1 = g_wgt[r1];
    const __half2* y0p = (const __half2*)(g_yh + (size_t)r0 * OUTD + c);
    const __half2* y1p = (const __half2*)(g_yh + (size_t)r1 * OUTD + c);
    float2 a0 = __half22float2(y0p[0]), a1 = __half22float2(y0p[1]);
    float2 b0 = __half22float2(y1p[0]), b1 = __half22float2(y1p[1]);
    float4 o;
    o.x = w0*a0.x + w1*b0.x;
    o.y = w0*a0.y + w1*b0.y;
    o.z = w0*a1.x + w1*b1.x;
    o.w = w0*a1.y + w1*b1.y;
    *(float4*)(out + (size_t)n * OUTD + c) = o;
}

// ---------------- launch: dual-stream expert-group pipeline ----------------
extern "C" void kernel_launch(void* const* d_in, const int* in_sizes, int n_in,
                              void* d_out, int out_size) {
    const float* x  = (const float*)d_in[0];
    const float* Wg = (const float*)d_in[1];
    const float* W1 = (const float*)d_in[2];
    const float* b1 = (const float*)d_in[3];
    const float* W2 = (const float*)d_in[4];
    const float* b2 = (const float*)d_in[5];
    float* out = (float*)d_out;

    static cudaStream_t s1 = nullptr;
    static cudaEvent_t evFork, evC1, evC2, evPlan, evG2b;
    static bool inited = false;
    if (!inited) {
        cudaStreamCreateWithFlags(&s1, cudaStreamNonBlocking);
        cudaEventCreateWithFlags(&evFork, cudaEventDisableTiming);
        cudaEventCreateWithFlags(&evC1,   cudaEventDisableTiming);
        cudaEventCreateWithFlags(&evC2,   cudaEventDisableTiming);
        cudaEventCreateWithFlags(&evPlan, cudaEventDisableTiming);
        cudaEventCreateWithFlags(&evG2b,  cudaEventDisableTiming);
        cudaFuncSetAttribute(gemm_hmma<DIMD, HID, true>,
                             cudaFuncAttributeMaxDynamicSharedMemorySize, SMEM_TOTAL);
        cudaFuncSetAttribute(gemm_hmma<HID, OUTD, false>,
                             cudaFuncAttributeMaxDynamicSharedMemorySize, SMEM_TOTAL);
        inited = true;
    }

    // fork: weight converts on side stream
    cudaEventRecord(evFork, 0);
    cudaStreamWaitEvent(s1, evFork, 0);
    convert1_kernel<<<NE * DIMD * HID / 1024, 256, 0, s1>>>((const float4*)W1);
    cudaEventRecord(evC1, s1);
    convert2_kernel<<<NE * HID * OUTD / 1024, 256, 0, s1>>>((const float4*)W2);
    cudaEventRecord(evC2, s1);

    // main: gate + parallel plan
    gate_kernel<<<N_TOK / 32, 256>>>(x, Wg);
    plan_count_kernel<<<NE, 256>>>();
    plan_scatter_kernel<<<NE, 256>>>();
    cudaEventRecord(evPlan, 0);

    // group A (experts 0-3) on stream0: G1a -> G2a
    cudaStreamWaitEvent(0, evC1, 0);
    {
        dim3 grid(RMAX / 128, HID / 256, 4);
        gemm_hmma<DIMD, HID, true><<<grid, 256, SMEM_TOTAL>>>(b1, 0);
    }
    cudaStreamWaitEvent(0, evC2, 0);
    {
        dim3 grid(RMAX / 128, OUTD / 256, 4);
        gemm_hmma<HID, OUTD, false><<<grid, 256, SMEM_TOTAL>>>(b2, 0);
    }

    // group B (experts 4-7) on s1: G1b -> G2b (after converts in s1 order)
    cudaStreamWaitEvent(s1, evPlan, 0);
    {
        dim3 grid(RMAX / 128, HID / 256, 4);
        gemm_hmma<DIMD, HID, true><<<grid, 256, SMEM_TOTAL, s1>>>(b1, 4);
    }
    {
        dim3 grid(RMAX / 128, OUTD / 256, 4);
        gemm_hmma<HID, OUTD, false><<<grid, 256, SMEM_TOTAL, s1>>>(b2, 4);
    }
    cudaEventRecord(evG2b, s1);

    // join + combine
    cudaStreamWaitEvent(0, evG2b, 0);
    combine_kernel<<<(N_TOK * OUTD / 4 + 255) / 256, 256>>>(out);
}